// round 8
// baseline (speedup 1.0000x reference)
#include <cuda_runtime.h>
#include <cuda_fp16.h>
#include <cstdint>

// Shapes: X [8192,4096] fp32, W [4096,4096], b[4096], out [8192,4096] fp32.
static const int MTOT = 8192;
static const int NTOT = 4096;
static const int KTOT = 4096;

// GEMM tiling: CTA 128x128xBK64, 128 threads (4 warps, 2x2, 64x64 warp tile),
// 2 CTAs/SM. f16 accumulators within a kt, promoted to fp32 per kt.
#define BM 128
#define BN 128
#define BK 64
#define SSTAGE 32768        // Xh 16K + Wh 16K
#define NSTAGES 3
#define NCHUNK (KTOT / BK)  // 64

// Scratch (__device__ globals; allocation-free rule)
__device__ __align__(1024) __half g_Xh[(size_t)MTOT * KTOT];
__device__ __align__(1024) __half g_Wh[(size_t)NTOT * KTOT];

// ---------------------------------------------------------------------------
// Kernel 1: convert X to fp16
// ---------------------------------------------------------------------------
__global__ void split_x_kernel(const float4* __restrict__ x, int n4) {
    int i = blockIdx.x * blockDim.x + threadIdx.x;
    if (i >= n4) return;
    float4 v = x[i];
    ushort4 hh;
    hh.x = __half_as_ushort(__float2half_rn(v.x));
    hh.y = __half_as_ushort(__float2half_rn(v.y));
    hh.z = __half_as_ushort(__float2half_rn(v.z));
    hh.w = __half_as_ushort(__float2half_rn(v.w));
    reinterpret_cast<ushort4*>(g_Xh)[i] = hh;
}

// ---------------------------------------------------------------------------
// Kernel 2: W_eff = W + B_u A_u + B_s A_s  ->  fp16
//   delta_s[n,k] = sum_t B0[n%2048, t] * A0[(t + n/2048 - k/2048) mod 56, k%2048]
// ---------------------------------------------------------------------------
__global__ void build_w_kernel(const float* __restrict__ W,
                               const float* __restrict__ A_u,
                               const float* __restrict__ B_u,
                               const float* __restrict__ A0,
                               const float* __restrict__ B0) {
    __shared__ float sAu[8][128];
    __shared__ float sA0[56][128];
    __shared__ float sBu[32][8];
    __shared__ float sB0[32][56];

    int tid = threadIdx.x;                 // 0..127
    int k = blockIdx.x * 128 + tid;
    int i = k >> 11;
    int kk = k & 2047;
    int nbase = blockIdx.y * 32;
    int j = nbase >> 11;
    int nb2 = nbase & 2047;

#pragma unroll
    for (int u = 0; u < 8; u++) sAu[u][tid] = A_u[u * 4096 + k];
#pragma unroll
    for (int r = 0; r < 56; r++) sA0[r][tid] = A0[r * 2048 + kk];
    for (int idx = tid; idx < 32 * 8; idx += 128) {
        int ln = idx >> 3, u = idx & 7;
        sBu[ln][u] = B_u[(nbase + ln) * 8 + u];
    }
    for (int idx = tid; idx < 32 * 56; idx += 128) {
        int ln = idx / 56, t = idx % 56;
        sB0[ln][t] = B0[(nb2 + ln) * 56 + t];
    }
    __syncthreads();

    int d = j - i;  // -1, 0, or 1
    for (int ln = 0; ln < 32; ln++) {
        int n = nbase + ln;
        float acc = W[(size_t)n * 4096 + k];
#pragma unroll
        for (int u = 0; u < 8; u++) acc += sBu[ln][u] * sAu[u][tid];
#pragma unroll
        for (int t = 0; t < 56; t++) {
            int rr = t + d;
            rr = (rr >= 56) ? rr - 56 : (rr < 0 ? rr + 56 : rr);
            acc += sB0[ln][t] * sA0[rr][tid];
        }
        g_Wh[(size_t)n * 4096 + k] = __float2half_rn(acc);
    }
}

// ---------------------------------------------------------------------------
// Kernel 3: GEMM  out = Xh * Wh^T + b
// fp16 inputs, f16 accumulation within each K=64 chunk (2x HMMA rate),
// promoted into fp32 shadow accumulators once per chunk.
// CTA 128x128xBK64, 128 threads (4 warps, 2x2), warp tile 64x64,
// 3-stage cp.async pipeline, 2 CTAs/SM.
// ---------------------------------------------------------------------------
__device__ __forceinline__ void cp16(uint32_t dst, const void* src) {
    asm volatile("cp.async.cg.shared.global [%0], [%1], 16;" :: "r"(dst), "l"(src));
}
__device__ __forceinline__ void ldsm4(uint32_t& r0, uint32_t& r1, uint32_t& r2,
                                      uint32_t& r3, uint32_t addr) {
    asm volatile("ldmatrix.sync.aligned.m8n8.x4.shared.b16 {%0,%1,%2,%3}, [%4];"
                 : "=r"(r0), "=r"(r1), "=r"(r2), "=r"(r3) : "r"(addr));
}
// f16-accumulator MMA: d/c are 2 regs of f16x2 (same value positions as the
// 4-reg f32 form: reg0={row r, cols c,c+1}, reg1={row r+8, cols c,c+1}).
__device__ __forceinline__ void mma16816_h(uint32_t& c0, uint32_t& c1,
                                           const uint32_t* a,
                                           uint32_t b0, uint32_t b1) {
    asm volatile(
        "mma.sync.aligned.m16n8k16.row.col.f16.f16.f16.f16 "
        "{%0,%1},{%2,%3,%4,%5},{%6,%7},{%0,%1};"
        : "+r"(c0), "+r"(c1)
        : "r"(a[0]), "r"(a[1]), "r"(a[2]), "r"(a[3]), "r"(b0), "r"(b1));
}

__global__ void __launch_bounds__(128, 2)
gemm_kernel(const float* __restrict__ bias, float* __restrict__ out) {
    extern __shared__ char smem[];
    uint32_t sbase = (uint32_t)__cvta_generic_to_shared(smem);
    int tid = threadIdx.x;
    int lane = tid & 31, warp = tid >> 5;
    int wm = warp >> 1;   // 0..1 : 64 rows each
    int wn = warp & 1;    // 0..1 : 64 cols each
    int bm = blockIdx.y, bn = blockIdx.x;

    const __half* gXh = g_Xh + (size_t)bm * BM * 4096;
    const __half* gWh = g_Wh + (size_t)bn * BN * 4096;

    auto load_stage = [&](int s, int kt) {
        uint32_t st = sbase + s * SSTAGE;
#pragma unroll
        for (int i2 = 0; i2 < 8; i2++) {
            int idx = tid + i2 * 128;
            int r = idx >> 3, c = idx & 7;
            uint32_t dst = st + r * 128 + ((c ^ (r & 7)) << 4);
            cp16(dst, gXh + (size_t)r * 4096 + kt * BK + c * 8);
        }
#pragma unroll
        for (int i2 = 0; i2 < 8; i2++) {
            int idx = tid + i2 * 128;
            int r = idx >> 3, c = idx & 7;
            uint32_t dst = st + 16384 + r * 128 + ((c ^ (r & 7)) << 4);
            cp16(dst, gWh + (size_t)r * 4096 + kt * BK + c * 8);
        }
    };

    float acc[4][8][4];
#pragma unroll
    for (int a = 0; a < 4; a++)
#pragma unroll
        for (int b = 0; b < 8; b++)
#pragma unroll
            for (int c = 0; c < 4; c++) acc[a][b][c] = 0.0f;

    load_stage(0, 0);
    asm volatile("cp.async.commit_group;");
    load_stage(1, 1);
    asm volatile("cp.async.commit_group;");

    int arow = wm * 64 + (lane & 15);
    int nrow0 = wn * 64 + (lane & 7) + ((lane >> 4) << 3);

    for (int kt = 0; kt < NCHUNK; kt++) {
        asm volatile("cp.async.wait_group 1;");
        __syncthreads();
        int ls = kt + 2;
        if (ls < NCHUNK) load_stage(ls % NSTAGES, ls);
        asm volatile("cp.async.commit_group;");

        uint32_t st = sbase + (kt % NSTAGES) * SSTAGE;

        // f16 chunk accumulators (zeroed per kt)
        uint32_t acch[4][8][2];
#pragma unroll
        for (int mt = 0; mt < 4; mt++)
#pragma unroll
            for (int nt = 0; nt < 8; nt++) {
                acch[mt][nt][0] = 0u;
                acch[mt][nt][1] = 0u;
            }

#pragma unroll
        for (int ks = 0; ks < 4; ks++) {
            uint32_t ah[4][4], bh[4][4];
            int ach = ks * 2 + (lane >> 4);
            int bch = ks * 2 + ((lane >> 3) & 1);
#pragma unroll
            for (int mt = 0; mt < 4; mt++) {
                int row = arow + mt * 16;
                uint32_t off = row * 128 + ((ach ^ (row & 7)) << 4);
                ldsm4(ah[mt][0], ah[mt][1], ah[mt][2], ah[mt][3], st + off);
            }
#pragma unroll
            for (int q = 0; q < 4; q++) {
                int row = nrow0 + q * 16;
                uint32_t off = row * 128 + ((bch ^ (row & 7)) << 4);
                ldsm4(bh[q][0], bh[q][1], bh[q][2], bh[q][3], st + 16384 + off);
            }
#pragma unroll
            for (int mt = 0; mt < 4; mt++) {
#pragma unroll
                for (int nt = 0; nt < 8; nt++) {
                    int q = nt >> 1, o = (nt & 1) * 2;
                    mma16816_h(acch[mt][nt][0], acch[mt][nt][1], ah[mt],
                               bh[q][o], bh[q][o + 1]);
                }
            }
        }

        // Promote chunk f16 partials into fp32 accumulators
#pragma unroll
        for (int mt = 0; mt < 4; mt++)
#pragma unroll
            for (int nt = 0; nt < 8; nt++) {
                float2 lo = __half22float2(
                    *reinterpret_cast<__half2*>(&acch[mt][nt][0]));
                float2 hi = __half22float2(
                    *reinterpret_cast<__half2*>(&acch[mt][nt][1]));
                acc[mt][nt][0] += lo.x;
                acc[mt][nt][1] += lo.y;
                acc[mt][nt][2] += hi.x;
                acc[mt][nt][3] += hi.y;
            }
        __syncthreads();
    }

    // Epilogue: add bias, write fp32 directly
    const float* bptr = bias + bn * BN + wn * 64;
    size_t outbase = (size_t)(bm * BM + wm * 64) * 4096 + bn * BN + wn * 64;
    int gid = lane >> 2, tig = lane & 3;
#pragma unroll
    for (int nt = 0; nt < 8; nt++) {
        int c = nt * 8 + tig * 2;
        float b0 = bptr[c], b1 = bptr[c + 1];
#pragma unroll
        for (int mt = 0; mt < 4; mt++) {
            int r = mt * 16 + gid;
            float2 v0 = make_float2(acc[mt][nt][0] + b0, acc[mt][nt][1] + b1);
            float2 v1 = make_float2(acc[mt][nt][2] + b0, acc[mt][nt][3] + b1);
            *reinterpret_cast<float2*>(out + outbase + (size_t)r * 4096 + c) = v0;
            *reinterpret_cast<float2*>(out + outbase + (size_t)(r + 8) * 4096 + c) = v1;
        }
    }
}

// ---------------------------------------------------------------------------
extern "C" void kernel_launch(void* const* d_in, const int* in_sizes, int n_in,
                              void* d_out, int out_size) {
    const float* x  = (const float*)d_in[0];
    const float* W  = (const float*)d_in[1];
    const float* b  = (const float*)d_in[2];
    const float* Au = (const float*)d_in[3];
    const float* Bu = (const float*)d_in[4];
    const float* A0 = (const float*)d_in[5];
    const float* B0 = (const float*)d_in[6];
    float* out = (float*)d_out;

    int n4 = (MTOT * KTOT) / 4;
    split_x_kernel<<<(n4 + 255) / 256, 256>>>((const float4*)x, n4);
    build_w_kernel<<<dim3(KTOT / 128, NTOT / 32), 128>>>(W, Au, Bu, A0, B0);

    cudaFuncSetAttribute(gemm_kernel,
                         cudaFuncAttributeMaxDynamicSharedMemorySize,
                         NSTAGES * SSTAGE);
    gemm_kernel<<<dim3(NTOT / BN, MTOT / BM), 128, NSTAGES * SSTAGE>>>(b, out);
}

// round 9
// speedup vs baseline: 1.2260x; 1.2260x over previous
#include <cuda_runtime.h>
#include <cuda_fp16.h>
#include <cstdint>

// Shapes: X [8192,4096] fp32, W [4096,4096], b[4096], out [8192,4096] fp32.
static const int MTOT = 8192;
static const int NTOT = 4096;
static const int KTOT = 4096;

// GEMM tiling: CTA 128x128xBK64, 128 threads (4 warps, 2x2, 64x64 warp tile),
// 2 CTAs/SM, register double-buffered fragments.
#define BM 128
#define BN 128
#define BK 64
#define SSTAGE 32768        // Xh 16K + Wh 16K
#define NSTAGES 3
#define NCHUNK (KTOT / BK)  // 64

// Scratch (__device__ globals; allocation-free rule)
__device__ __align__(1024) __half g_Xh[(size_t)MTOT * KTOT];
__device__ __align__(1024) __half g_Wh[(size_t)NTOT * KTOT];

// ---------------------------------------------------------------------------
// Kernel 1: convert X to fp16
// ---------------------------------------------------------------------------
__global__ void split_x_kernel(const float4* __restrict__ x, int n4) {
    int i = blockIdx.x * blockDim.x + threadIdx.x;
    if (i >= n4) return;
    float4 v = x[i];
    ushort4 hh;
    hh.x = __half_as_ushort(__float2half_rn(v.x));
    hh.y = __half_as_ushort(__float2half_rn(v.y));
    hh.z = __half_as_ushort(__float2half_rn(v.z));
    hh.w = __half_as_ushort(__float2half_rn(v.w));
    reinterpret_cast<ushort4*>(g_Xh)[i] = hh;
}

// ---------------------------------------------------------------------------
// Kernel 2: W_eff = W + B_u A_u + B_s A_s  ->  fp16
//   delta_s[n,k] = sum_t B0[n%2048, t] * A0[(t + n/2048 - k/2048) mod 56, k%2048]
// ---------------------------------------------------------------------------
__global__ void build_w_kernel(const float* __restrict__ W,
                               const float* __restrict__ A_u,
                               const float* __restrict__ B_u,
                               const float* __restrict__ A0,
                               const float* __restrict__ B0) {
    __shared__ float sAu[8][128];
    __shared__ float sA0[56][128];
    __shared__ float sBu[32][8];
    __shared__ float sB0[32][56];

    int tid = threadIdx.x;                 // 0..127
    int k = blockIdx.x * 128 + tid;
    int i = k >> 11;
    int kk = k & 2047;
    int nbase = blockIdx.y * 32;
    int j = nbase >> 11;
    int nb2 = nbase & 2047;

#pragma unroll
    for (int u = 0; u < 8; u++) sAu[u][tid] = A_u[u * 4096 + k];
#pragma unroll
    for (int r = 0; r < 56; r++) sA0[r][tid] = A0[r * 2048 + kk];
    for (int idx = tid; idx < 32 * 8; idx += 128) {
        int ln = idx >> 3, u = idx & 7;
        sBu[ln][u] = B_u[(nbase + ln) * 8 + u];
    }
    for (int idx = tid; idx < 32 * 56; idx += 128) {
        int ln = idx / 56, t = idx % 56;
        sB0[ln][t] = B0[(nb2 + ln) * 56 + t];
    }
    __syncthreads();

    int d = j - i;  // -1, 0, or 1
    for (int ln = 0; ln < 32; ln++) {
        int n = nbase + ln;
        float acc = W[(size_t)n * 4096 + k];
#pragma unroll
        for (int u = 0; u < 8; u++) acc += sBu[ln][u] * sAu[u][tid];
#pragma unroll
        for (int t = 0; t < 56; t++) {
            int rr = t + d;
            rr = (rr >= 56) ? rr - 56 : (rr < 0 ? rr + 56 : rr);
            acc += sB0[ln][t] * sA0[rr][tid];
        }
        g_Wh[(size_t)n * 4096 + k] = __float2half_rn(acc);
    }
}

// ---------------------------------------------------------------------------
// Kernel 3: GEMM  out = Xh * Wh^T + b   (fp16 inputs, fp32 accum)
// CTA 128x128xBK64, 128 threads (4 warps, 2x2), warp tile 64x64,
// 3-stage cp.async pipeline, 2 CTAs/SM, register double-buffered ks loop,
// single barrier per kt.
// ---------------------------------------------------------------------------
__device__ __forceinline__ void cp16(uint32_t dst, const void* src) {
    asm volatile("cp.async.cg.shared.global [%0], [%1], 16;" :: "r"(dst), "l"(src));
}
__device__ __forceinline__ void ldsm4(uint32_t& r0, uint32_t& r1, uint32_t& r2,
                                      uint32_t& r3, uint32_t addr) {
    asm volatile("ldmatrix.sync.aligned.m8n8.x4.shared.b16 {%0,%1,%2,%3}, [%4];"
                 : "=r"(r0), "=r"(r1), "=r"(r2), "=r"(r3) : "r"(addr));
}
__device__ __forceinline__ void mma16816(float* c, const uint32_t* a,
                                         uint32_t b0, uint32_t b1) {
    asm volatile(
        "mma.sync.aligned.m16n8k16.row.col.f32.f16.f16.f32 "
        "{%0,%1,%2,%3},{%4,%5,%6,%7},{%8,%9},{%0,%1,%2,%3};"
        : "+f"(c[0]), "+f"(c[1]), "+f"(c[2]), "+f"(c[3])
        : "r"(a[0]), "r"(a[1]), "r"(a[2]), "r"(a[3]), "r"(b0), "r"(b1));
}

__global__ void __launch_bounds__(128, 2)
gemm_kernel(const float* __restrict__ bias, float* __restrict__ out) {
    extern __shared__ char smem[];
    uint32_t sbase = (uint32_t)__cvta_generic_to_shared(smem);
    int tid = threadIdx.x;
    int lane = tid & 31, warp = tid >> 5;
    int wm = warp >> 1;   // 0..1 : 64 rows each
    int wn = warp & 1;    // 0..1 : 64 cols each
    int bm = blockIdx.y, bn = blockIdx.x;

    const __half* gXh = g_Xh + (size_t)bm * BM * 4096;
    const __half* gWh = g_Wh + (size_t)bn * BN * 4096;

    auto load_stage = [&](int s, int kt) {
        uint32_t st = sbase + s * SSTAGE;
#pragma unroll
        for (int i2 = 0; i2 < 8; i2++) {
            int idx = tid + i2 * 128;
            int r = idx >> 3, c = idx & 7;
            uint32_t dst = st + r * 128 + ((c ^ (r & 7)) << 4);
            cp16(dst, gXh + (size_t)r * 4096 + kt * BK + c * 8);
        }
#pragma unroll
        for (int i2 = 0; i2 < 8; i2++) {
            int idx = tid + i2 * 128;
            int r = idx >> 3, c = idx & 7;
            uint32_t dst = st + 16384 + r * 128 + ((c ^ (r & 7)) << 4);
            cp16(dst, gWh + (size_t)r * 4096 + kt * BK + c * 8);
        }
    };

    float acc[4][8][4];
#pragma unroll
    for (int a = 0; a < 4; a++)
#pragma unroll
        for (int b = 0; b < 8; b++)
#pragma unroll
            for (int c = 0; c < 4; c++) acc[a][b][c] = 0.0f;

    load_stage(0, 0);
    asm volatile("cp.async.commit_group;");
    load_stage(1, 1);
    asm volatile("cp.async.commit_group;");

    int arow = wm * 64 + (lane & 15);
    int nrow0 = wn * 64 + (lane & 7) + ((lane >> 4) << 3);

    uint32_t ah[2][4][4];   // [buf][mt][frag]
    uint32_t bh[2][4][4];   // [buf][q][frag]

    for (int kt = 0; kt < NCHUNK; kt++) {
        asm volatile("cp.async.wait_group 1;");
        __syncthreads();
        int ls = kt + 2;
        if (ls < NCHUNK) load_stage(ls % NSTAGES, ls);
        asm volatile("cp.async.commit_group;");

        uint32_t st = sbase + (kt % NSTAGES) * SSTAGE;

        auto ldfrag = [&](int buf, int ks) {
            int ach = ks * 2 + (lane >> 4);
            int bch = ks * 2 + ((lane >> 3) & 1);
#pragma unroll
            for (int mt = 0; mt < 4; mt++) {
                int row = arow + mt * 16;
                uint32_t off = row * 128 + ((ach ^ (row & 7)) << 4);
                ldsm4(ah[buf][mt][0], ah[buf][mt][1], ah[buf][mt][2],
                      ah[buf][mt][3], st + off);
            }
#pragma unroll
            for (int q = 0; q < 4; q++) {
                int row = nrow0 + q * 16;
                uint32_t off = row * 128 + ((bch ^ (row & 7)) << 4);
                ldsm4(bh[buf][q][0], bh[buf][q][1], bh[buf][q][2],
                      bh[buf][q][3], st + 16384 + off);
            }
        };

        ldfrag(0, 0);
#pragma unroll
        for (int ks = 0; ks < 4; ks++) {
            int cur = ks & 1, nxt = cur ^ 1;
            if (ks < 3) ldfrag(nxt, ks + 1);
#pragma unroll
            for (int mt = 0; mt < 4; mt++) {
#pragma unroll
                for (int nt = 0; nt < 8; nt++) {
                    int q = nt >> 1, o = (nt & 1) * 2;
                    mma16816(acc[mt][nt], ah[cur][mt], bh[cur][q][o],
                             bh[cur][q][o + 1]);
                }
            }
        }
        // NOTE: no end-of-loop barrier. The top-of-loop __syncthreads at kt+1
        // orders all reads of stage kt%3 before the writes to it at kt+3.
    }

    // Epilogue: add bias, write fp32 directly
    const float* bptr = bias + bn * BN + wn * 64;
    size_t outbase = (size_t)(bm * BM + wm * 64) * 4096 + bn * BN + wn * 64;
    int gid = lane >> 2, tig = lane & 3;
#pragma unroll
    for (int nt = 0; nt < 8; nt++) {
        int c = nt * 8 + tig * 2;
        float b0 = bptr[c], b1 = bptr[c + 1];
#pragma unroll
        for (int mt = 0; mt < 4; mt++) {
            int r = mt * 16 + gid;
            float2 v0 = make_float2(acc[mt][nt][0] + b0, acc[mt][nt][1] + b1);
            float2 v1 = make_float2(acc[mt][nt][2] + b0, acc[mt][nt][3] + b1);
            *reinterpret_cast<float2*>(out + outbase + (size_t)r * 4096 + c) = v0;
            *reinterpret_cast<float2*>(out + outbase + (size_t)(r + 8) * 4096 + c) = v1;
        }
    }
}

// ---------------------------------------------------------------------------
extern "C" void kernel_launch(void* const* d_in, const int* in_sizes, int n_in,
                              void* d_out, int out_size) {
    const float* x  = (const float*)d_in[0];
    const float* W  = (const float*)d_in[1];
    const float* b  = (const float*)d_in[2];
    const float* Au = (const float*)d_in[3];
    const float* Bu = (const float*)d_in[4];
    const float* A0 = (const float*)d_in[5];
    const float* B0 = (const float*)d_in[6];
    float* out = (float*)d_out;

    int n4 = (MTOT * KTOT) / 4;
    split_x_kernel<<<(n4 + 255) / 256, 256>>>((const float4*)x, n4);
    build_w_kernel<<<dim3(KTOT / 128, NTOT / 32), 128>>>(W, Au, Bu, A0, B0);

    cudaFuncSetAttribute(gemm_kernel,
                         cudaFuncAttributeMaxDynamicSharedMemorySize,
                         NSTAGES * SSTAGE);
    gemm_kernel<<<dim3(NTOT / BN, MTOT / BM), 128, NSTAGES * SSTAGE>>>(b, out);
}

// round 10
// speedup vs baseline: 1.2734x; 1.0386x over previous
#include <cuda_runtime.h>
#include <cuda.h>
#include <cuda_fp16.h>
#include <cstdint>

// Shapes: X [8192,4096] fp32, W [4096,4096], b[4096], out [8192,4096] fp32.
static const int MTOT = 8192;
static const int NTOT = 4096;
static const int KTOT = 4096;

// GEMM tiling: CTA 128x128xBK64, 128 threads (4 warps, 2x2, 64x64 warp tile),
// 2 CTAs/SM, TMA loads + mbarrier pipeline, register double-buffered ks loop.
#define BM 128
#define BN 128
#define BK 64
#define SSTAGE 32768        // Xh 16K + Wh 16K
#define NSTAGES 3
#define SMEM_DATA_OFF 1024
#define NCHUNK (KTOT / BK)  // 64

// Scratch (__device__ globals; allocation-free rule)
__device__ __align__(1024) __half g_Xh[(size_t)MTOT * KTOT];
__device__ __align__(1024) __half g_Wh[(size_t)NTOT * KTOT];

// ---------------------------------------------------------------------------
// Kernel 1: convert X to fp16
// ---------------------------------------------------------------------------
__global__ void split_x_kernel(const float4* __restrict__ x, int n4) {
    int i = blockIdx.x * blockDim.x + threadIdx.x;
    if (i >= n4) return;
    float4 v = x[i];
    ushort4 hh;
    hh.x = __half_as_ushort(__float2half_rn(v.x));
    hh.y = __half_as_ushort(__float2half_rn(v.y));
    hh.z = __half_as_ushort(__float2half_rn(v.z));
    hh.w = __half_as_ushort(__float2half_rn(v.w));
    reinterpret_cast<ushort4*>(g_Xh)[i] = hh;
}

// ---------------------------------------------------------------------------
// Kernel 2: W_eff = W + B_u A_u + B_s A_s  ->  fp16
//   delta_s[n,k] = sum_t B0[n%2048, t] * A0[(t + n/2048 - k/2048) mod 56, k%2048]
// ---------------------------------------------------------------------------
__global__ void build_w_kernel(const float* __restrict__ W,
                               const float* __restrict__ A_u,
                               const float* __restrict__ B_u,
                               const float* __restrict__ A0,
                               const float* __restrict__ B0) {
    __shared__ float sAu[8][128];
    __shared__ float sA0[56][128];
    __shared__ float sBu[32][8];
    __shared__ float sB0[32][56];

    int tid = threadIdx.x;                 // 0..127
    int k = blockIdx.x * 128 + tid;
    int i = k >> 11;
    int kk = k & 2047;
    int nbase = blockIdx.y * 32;
    int j = nbase >> 11;
    int nb2 = nbase & 2047;

#pragma unroll
    for (int u = 0; u < 8; u++) sAu[u][tid] = A_u[u * 4096 + k];
#pragma unroll
    for (int r = 0; r < 56; r++) sA0[r][tid] = A0[r * 2048 + kk];
    for (int idx = tid; idx < 32 * 8; idx += 128) {
        int ln = idx >> 3, u = idx & 7;
        sBu[ln][u] = B_u[(nbase + ln) * 8 + u];
    }
    for (int idx = tid; idx < 32 * 56; idx += 128) {
        int ln = idx / 56, t = idx % 56;
        sB0[ln][t] = B0[(nb2 + ln) * 56 + t];
    }
    __syncthreads();

    int d = j - i;  // -1, 0, or 1
    for (int ln = 0; ln < 32; ln++) {
        int n = nbase + ln;
        float acc = W[(size_t)n * 4096 + k];
#pragma unroll
        for (int u = 0; u < 8; u++) acc += sBu[ln][u] * sAu[u][tid];
#pragma unroll
        for (int t = 0; t < 56; t++) {
            int rr = t + d;
            rr = (rr >= 56) ? rr - 56 : (rr < 0 ? rr + 56 : rr);
            acc += sB0[ln][t] * sA0[rr][tid];
        }
        g_Wh[(size_t)n * 4096 + k] = __float2half_rn(acc);
    }
}

// ---------------------------------------------------------------------------
// PTX helpers (sm_90 base-target features only)
// ---------------------------------------------------------------------------
__device__ __forceinline__ void ldsm4(uint32_t& r0, uint32_t& r1, uint32_t& r2,
                                      uint32_t& r3, uint32_t addr) {
    asm volatile("ldmatrix.sync.aligned.m8n8.x4.shared.b16 {%0,%1,%2,%3}, [%4];"
                 : "=r"(r0), "=r"(r1), "=r"(r2), "=r"(r3) : "r"(addr));
}
__device__ __forceinline__ void mma16816(float* c, const uint32_t* a,
                                         uint32_t b0, uint32_t b1) {
    asm volatile(
        "mma.sync.aligned.m16n8k16.row.col.f32.f16.f16.f32 "
        "{%0,%1,%2,%3},{%4,%5,%6,%7},{%8,%9},{%0,%1,%2,%3};"
        : "+f"(c[0]), "+f"(c[1]), "+f"(c[2]), "+f"(c[3])
        : "r"(a[0]), "r"(a[1]), "r"(a[2]), "r"(a[3]), "r"(b0), "r"(b1));
}
__device__ __forceinline__ void tma2d(uint32_t dst, const void* map, int x, int y,
                                      uint32_t mbar) {
    asm volatile(
        "cp.async.bulk.tensor.2d.shared::cta.global.tile.mbarrier::complete_tx::bytes "
        "[%0], [%1, {%2, %3}], [%4];"
        :: "r"(dst), "l"(map), "r"(x), "r"(y), "r"(mbar) : "memory");
}
#define MBAR_INIT(a, c) \
    asm volatile("mbarrier.init.shared.b64 [%0], %1;" :: "r"(a), "r"(c) : "memory")
#define MBAR_EXPECT_TX(a, b) \
    asm volatile("mbarrier.arrive.expect_tx.shared.b64 _, [%0], %1;" :: "r"(a), "r"(b) : "memory")
#define MBAR_WAIT(a, ph) do {                                                    \
    asm volatile("{\n .reg .pred P;\n"                                           \
        "WL_%=: mbarrier.try_wait.parity.acquire.cta.shared::cta.b64 P, [%0], %1;\n" \
        "@P bra WD_%=;\n bra WL_%=;\n WD_%=:\n}"                                 \
        :: "r"(a), "r"(ph) : "memory"); } while (0)

// ---------------------------------------------------------------------------
// Kernel 3: GEMM  out = Xh * Wh^T + b   (fp16 inputs, fp32 accum)
// TMA-fed 3-stage pipeline; SW128 tensormap swizzle == chunk^(row&7) XOR
// swizzle, so ldmatrix addressing is identical to the cp.async version.
// ---------------------------------------------------------------------------
__global__ void __launch_bounds__(128, 2)
gemm_kernel(const __grid_constant__ CUtensorMap mXh,
            const __grid_constant__ CUtensorMap mWh,
            const float* __restrict__ bias, float* __restrict__ out) {
    extern __shared__ char smem[];
    uint32_t sbase = (uint32_t)__cvta_generic_to_shared(smem);
    int tid = threadIdx.x;
    int lane = tid & 31, warp = tid >> 5;
    int wm = warp >> 1;   // 0..1 : 64 rows each
    int wn = warp & 1;    // 0..1 : 64 cols each
    int bm = blockIdx.y, bn = blockIdx.x;

    uint32_t full[NSTAGES] = {sbase, sbase + 8, sbase + 16};

    if (tid == 0) {
        MBAR_INIT(full[0], 1);
        MBAR_INIT(full[1], 1);
        MBAR_INIT(full[2], 1);
    }
    __syncthreads();

    auto issue_stage = [&](int s, int kt) {
        uint32_t st = sbase + SMEM_DATA_OFF + s * SSTAGE;
        MBAR_EXPECT_TX(full[s], SSTAGE);
        tma2d(st,         &mXh, kt * BK, bm * BM, full[s]);
        tma2d(st + 16384, &mWh, kt * BK, bn * BN, full[s]);
    };

    if (tid == 0) {
        issue_stage(0, 0);
        issue_stage(1, 1);
    }

    float acc[4][8][4];
#pragma unroll
    for (int a = 0; a < 4; a++)
#pragma unroll
        for (int b = 0; b < 8; b++)
#pragma unroll
            for (int c = 0; c < 4; c++) acc[a][b][c] = 0.0f;

    int arow = wm * 64 + (lane & 15);
    int nrow0 = wn * 64 + (lane & 7) + ((lane >> 4) << 3);

    uint32_t ah[2][4][4];   // [buf][mt][frag]
    uint32_t bh[2][4][4];   // [buf][q][frag]
    int ph[NSTAGES] = {0, 0, 0};

    for (int kt = 0; kt < NCHUNK; kt++) {
        int cs = kt % NSTAGES;
        // All warps finished reading stage (kt+2)%3 == (kt-1)%3 before this
        // barrier, so it is safe to overwrite via TMA.
        __syncthreads();
        if (tid == 0 && kt + 2 < NCHUNK) issue_stage((kt + 2) % NSTAGES, kt + 2);
        MBAR_WAIT(full[cs], ph[cs]);
        ph[cs] ^= 1;

        uint32_t st = sbase + SMEM_DATA_OFF + cs * SSTAGE;

        auto ldfrag = [&](int buf, int ks) {
            int ach = ks * 2 + (lane >> 4);
            int bch = ks * 2 + ((lane >> 3) & 1);
#pragma unroll
            for (int mt = 0; mt < 4; mt++) {
                int row = arow + mt * 16;
                uint32_t off = row * 128 + ((ach ^ (row & 7)) << 4);
                ldsm4(ah[buf][mt][0], ah[buf][mt][1], ah[buf][mt][2],
                      ah[buf][mt][3], st + off);
            }
#pragma unroll
            for (int q = 0; q < 4; q++) {
                int row = nrow0 + q * 16;
                uint32_t off = row * 128 + ((bch ^ (row & 7)) << 4);
                ldsm4(bh[buf][q][0], bh[buf][q][1], bh[buf][q][2],
                      bh[buf][q][3], st + 16384 + off);
            }
        };

        ldfrag(0, 0);
#pragma unroll
        for (int ks = 0; ks < 4; ks++) {
            int cur = ks & 1, nxt = cur ^ 1;
            if (ks < 3) ldfrag(nxt, ks + 1);
#pragma unroll
            for (int mt = 0; mt < 4; mt++) {
#pragma unroll
                for (int nt = 0; nt < 8; nt++) {
                    int q = nt >> 1, o = (nt & 1) * 2;
                    mma16816(acc[mt][nt], ah[cur][mt], bh[cur][q][o],
                             bh[cur][q][o + 1]);
                }
            }
        }
    }

    // Epilogue: add bias, write fp32 directly
    const float* bptr = bias + bn * BN + wn * 64;
    size_t outbase = (size_t)(bm * BM + wm * 64) * 4096 + bn * BN + wn * 64;
    int gid = lane >> 2, tig = lane & 3;
#pragma unroll
    for (int nt = 0; nt < 8; nt++) {
        int c = nt * 8 + tig * 2;
        float b0 = bptr[c], b1 = bptr[c + 1];
#pragma unroll
        for (int mt = 0; mt < 4; mt++) {
            int r = mt * 16 + gid;
            float2 v0 = make_float2(acc[mt][nt][0] + b0, acc[mt][nt][1] + b1);
            float2 v1 = make_float2(acc[mt][nt][2] + b0, acc[mt][nt][3] + b1);
            *reinterpret_cast<float2*>(out + outbase + (size_t)r * 4096 + c) = v0;
            *reinterpret_cast<float2*>(out + outbase + (size_t)(r + 8) * 4096 + c) = v1;
        }
    }
}

// ---------------------------------------------------------------------------
typedef CUresult (*EncodeFn)(CUtensorMap*, CUtensorMapDataType, cuuint32_t, void*,
                             const cuuint64_t*, const cuuint64_t*, const cuuint32_t*,
                             const cuuint32_t*, CUtensorMapInterleave, CUtensorMapSwizzle,
                             CUtensorMapL2promotion, CUtensorMapFloatOOBfill);

static void make_map(EncodeFn enc, CUtensorMap* m, void* ptr, uint64_t rows) {
    cuuint64_t dims[2] = {(cuuint64_t)KTOT, (cuuint64_t)rows};
    cuuint64_t strides[1] = {(cuuint64_t)KTOT * 2};
    cuuint32_t box[2] = {BK, BM};  // 64 cols (128 B) x 128 rows
    cuuint32_t es[2] = {1, 1};
    enc(m, CU_TENSOR_MAP_DATA_TYPE_BFLOAT16, 2, ptr, dims, strides, box, es,
        CU_TENSOR_MAP_INTERLEAVE_NONE, CU_TENSOR_MAP_SWIZZLE_128B,
        CU_TENSOR_MAP_L2_PROMOTION_L2_128B, CU_TENSOR_MAP_FLOAT_OOB_FILL_NONE);
}

extern "C" void kernel_launch(void* const* d_in, const int* in_sizes, int n_in,
                              void* d_out, int out_size) {
    const float* x  = (const float*)d_in[0];
    const float* W  = (const float*)d_in[1];
    const float* b  = (const float*)d_in[2];
    const float* Au = (const float*)d_in[3];
    const float* Bu = (const float*)d_in[4];
    const float* A0 = (const float*)d_in[5];
    const float* B0 = (const float*)d_in[6];
    float* out = (float*)d_out;

    void* fp = nullptr;
    cudaDriverEntryPointQueryResult qr;
    cudaGetDriverEntryPoint("cuTensorMapEncodeTiled", &fp, cudaEnableDefault, &qr);
    EncodeFn enc = (EncodeFn)fp;

    void *pXh, *pWh;
    cudaGetSymbolAddress(&pXh, g_Xh);
    cudaGetSymbolAddress(&pWh, g_Wh);
    CUtensorMap mXh, mWh;
    make_map(enc, &mXh, pXh, MTOT);
    make_map(enc, &mWh, pWh, NTOT);

    int n4 = (MTOT * KTOT) / 4;
    split_x_kernel<<<(n4 + 255) / 256, 256>>>((const float4*)x, n4);
    build_w_kernel<<<dim3(KTOT / 128, NTOT / 32), 128>>>(W, Au, Bu, A0, B0);

    int dsmem = SMEM_DATA_OFF + NSTAGES * SSTAGE;
    cudaFuncSetAttribute(gemm_kernel,
                         cudaFuncAttributeMaxDynamicSharedMemorySize, dsmem);
    gemm_kernel<<<dim3(NTOT / BN, MTOT / BM), 128, dsmem>>>(mXh, mWh, b, out);
}

// round 11
// speedup vs baseline: 1.5451x; 1.2133x over previous
#include <cuda_runtime.h>
#include <cuda.h>
#include <cuda_fp16.h>
#include <cstdint>

// Shapes: X [8192,4096] fp32, W [4096,4096], b[4096], out [8192,4096] fp32.
static const int MTOT = 8192;
static const int NTOT = 4096;
static const int KTOT = 4096;

// GEMM tiling: CTA 128x128xBK64, 128 threads (4 warps, 2x2, 64x64 warp tile),
// 2 CTAs/SM, TMA loads + mbarrier pipeline, register double-buffered ks loop.
#define BM 128
#define BN 128
#define BK 64
#define SSTAGE 32768        // Xh 16K + Wh 16K
#define NSTAGES 3
#define SMEM_DATA_OFF 1024
#define NCHUNK (KTOT / BK)  // 64

// Scratch (__device__ globals; allocation-free rule)
__device__ __align__(1024) __half g_Xh[(size_t)MTOT * KTOT];
__device__ __align__(1024) __half g_Wh[(size_t)NTOT * KTOT];
__device__ __align__(1024) __half g_Bc[(size_t)NTOT * 64];   // [n, u] fp16
__device__ __align__(1024) __half g_AcT[(size_t)KTOT * 64];  // [k, u] fp16

// ---------------------------------------------------------------------------
// Kernel 1: convert X to fp16
// ---------------------------------------------------------------------------
__global__ void split_x_kernel(const float4* __restrict__ x, int n4) {
    int i = blockIdx.x * blockDim.x + threadIdx.x;
    if (i >= n4) return;
    float4 v = x[i];
    ushort4 hh;
    hh.x = __half_as_ushort(__float2half_rn(v.x));
    hh.y = __half_as_ushort(__float2half_rn(v.y));
    hh.z = __half_as_ushort(__float2half_rn(v.z));
    hh.w = __half_as_ushort(__float2half_rn(v.w));
    reinterpret_cast<ushort4*>(g_Xh)[i] = hh;
}

// ---------------------------------------------------------------------------
// Kernel 1b: pack low-rank factors into fp16 concat form.
//   A_cat (rank u, in k):  u<8 -> A_u[u,k];  u>=8 -> A0[(u-8 - k/2048)%56, k%2048]
//   B_cat (out n, rank u): u<8 -> B_u[n,u];  u>=8 -> B0[n%2048, (u-8 - n/2048)%56]
// Stored as A_catT [k,64] and B_cat [n,64], both row-major fp16.
// ---------------------------------------------------------------------------
__global__ void pack_kernel(const float* __restrict__ A_u,
                            const float* __restrict__ B_u,
                            const float* __restrict__ A0,
                            const float* __restrict__ B0) {
    int idx = blockIdx.x * blockDim.x + threadIdx.x;  // 0 .. 4096*64-1
    if (idx >= KTOT * 64) return;
    int k = idx >> 6, u = idx & 63;  // also n = k for the B side

    float av, bv;
    if (u < 8) {
        av = A_u[u * 4096 + k];
        bv = B_u[k * 8 + u];
    } else {
        int r = u - 8;
        int ia = ((r - (k >> 11)) % 56 + 56) % 56;
        av = A0[ia * 2048 + (k & 2047)];
        int ib = ((r - (k >> 11)) % 56 + 56) % 56;  // n/2048 with n==k
        bv = B0[(k & 2047) * 56 + ib];
    }
    g_AcT[idx] = __float2half_rn(av);
    g_Bc[idx] = __float2half_rn(bv);
}

// ---------------------------------------------------------------------------
// PTX helpers (sm_90 base-target features only)
// ---------------------------------------------------------------------------
__device__ __forceinline__ void cp16(uint32_t dst, const void* src) {
    asm volatile("cp.async.cg.shared.global [%0], [%1], 16;" :: "r"(dst), "l"(src));
}
__device__ __forceinline__ void ldsm4(uint32_t& r0, uint32_t& r1, uint32_t& r2,
                                      uint32_t& r3, uint32_t addr) {
    asm volatile("ldmatrix.sync.aligned.m8n8.x4.shared.b16 {%0,%1,%2,%3}, [%4];"
                 : "=r"(r0), "=r"(r1), "=r"(r2), "=r"(r3) : "r"(addr));
}
__device__ __forceinline__ void mma16816(float* c, const uint32_t* a,
                                         uint32_t b0, uint32_t b1) {
    asm volatile(
        "mma.sync.aligned.m16n8k16.row.col.f32.f16.f16.f32 "
        "{%0,%1,%2,%3},{%4,%5,%6,%7},{%8,%9},{%0,%1,%2,%3};"
        : "+f"(c[0]), "+f"(c[1]), "+f"(c[2]), "+f"(c[3])
        : "r"(a[0]), "r"(a[1]), "r"(a[2]), "r"(a[3]), "r"(b0), "r"(b1));
}
__device__ __forceinline__ void tma2d(uint32_t dst, const void* map, int x, int y,
                                      uint32_t mbar) {
    asm volatile(
        "cp.async.bulk.tensor.2d.shared::cta.global.tile.mbarrier::complete_tx::bytes "
        "[%0], [%1, {%2, %3}], [%4];"
        :: "r"(dst), "l"(map), "r"(x), "r"(y), "r"(mbar) : "memory");
}
#define MBAR_INIT(a, c) \
    asm volatile("mbarrier.init.shared.b64 [%0], %1;" :: "r"(a), "r"(c) : "memory")
#define MBAR_EXPECT_TX(a, b) \
    asm volatile("mbarrier.arrive.expect_tx.shared.b64 _, [%0], %1;" :: "r"(a), "r"(b) : "memory")
#define MBAR_WAIT(a, ph) do {                                                    \
    asm volatile("{\n .reg .pred P;\n"                                           \
        "WL_%=: mbarrier.try_wait.parity.acquire.cta.shared::cta.b64 P, [%0], %1;\n" \
        "@P bra WD_%=;\n bra WL_%=;\n WD_%=:\n}"                                 \
        :: "r"(a), "r"(ph) : "memory"); } while (0)

// ---------------------------------------------------------------------------
// Kernel 2: W_eff = W + B_cat @ A_cat via tensor cores, store fp16.
// Block tile 128(n) x 128(k), K=64 (rank). 128 threads, 4 warps 2x2.
// ---------------------------------------------------------------------------
__global__ void __launch_bounds__(128, 2)
build_w_tc_kernel(const float* __restrict__ W) {
    __shared__ __align__(1024) char smem[32768];  // Bc 16K | AcT 16K
    uint32_t sbase = (uint32_t)__cvta_generic_to_shared(smem);
    int tid = threadIdx.x;
    int lane = tid & 31, warp = tid >> 5;
    int wm = warp >> 1;   // n-dim half
    int wn = warp & 1;    // k-dim half
    int bn = blockIdx.y;  // n tile
    int bk = blockIdx.x;  // k tile

    const __half* gB = g_Bc + (size_t)bn * 128 * 64;
    const __half* gA = g_AcT + (size_t)bk * 128 * 64;

    // Load both 128x64 fp16 tiles, swizzled (rows are 128 B = 8 chunks).
#pragma unroll
    for (int i2 = 0; i2 < 8; i2++) {
        int idx = tid + i2 * 128;
        int r = idx >> 3, c = idx & 7;
        uint32_t dst = sbase + r * 128 + ((c ^ (r & 7)) << 4);
        cp16(dst, gB + (size_t)r * 64 + c * 8);
    }
#pragma unroll
    for (int i2 = 0; i2 < 8; i2++) {
        int idx = tid + i2 * 128;
        int r = idx >> 3, c = idx & 7;
        uint32_t dst = sbase + 16384 + r * 128 + ((c ^ (r & 7)) << 4);
        cp16(dst, gA + (size_t)r * 64 + c * 8);
    }
    asm volatile("cp.async.commit_group;");
    asm volatile("cp.async.wait_group 0;");
    __syncthreads();

    float acc[4][8][4];
#pragma unroll
    for (int a = 0; a < 4; a++)
#pragma unroll
        for (int b = 0; b < 8; b++)
#pragma unroll
            for (int c = 0; c < 4; c++) acc[a][b][c] = 0.0f;

    int arow = wm * 64 + (lane & 15);
    int nrow0 = wn * 64 + (lane & 7) + ((lane >> 4) << 3);

#pragma unroll
    for (int ks = 0; ks < 4; ks++) {
        uint32_t ah[4][4], bh[4][4];
        int ach = ks * 2 + (lane >> 4);
        int bch = ks * 2 + ((lane >> 3) & 1);
#pragma unroll
        for (int mt = 0; mt < 4; mt++) {
            int row = arow + mt * 16;
            uint32_t off = row * 128 + ((ach ^ (row & 7)) << 4);
            ldsm4(ah[mt][0], ah[mt][1], ah[mt][2], ah[mt][3], sbase + off);
        }
#pragma unroll
        for (int q = 0; q < 4; q++) {
            int row = nrow0 + q * 16;
            uint32_t off = row * 128 + ((bch ^ (row & 7)) << 4);
            ldsm4(bh[q][0], bh[q][1], bh[q][2], bh[q][3], sbase + 16384 + off);
        }
#pragma unroll
        for (int mt = 0; mt < 4; mt++) {
#pragma unroll
            for (int nt = 0; nt < 8; nt++) {
                int q = nt >> 1, o = (nt & 1) * 2;
                mma16816(acc[mt][nt], ah[mt], bh[q][o], bh[q][o + 1]);
            }
        }
    }

    // Epilogue: Wh[n,k] = fp16(W[n,k] + delta)
    int gid = lane >> 2, tig = lane & 3;
    int nb = bn * 128 + wm * 64;
    int kb = bk * 128 + wn * 64;
#pragma unroll
    for (int nt = 0; nt < 8; nt++) {
        int c = kb + nt * 8 + tig * 2;
#pragma unroll
        for (int mt = 0; mt < 4; mt++) {
            int r0 = nb + mt * 16 + gid;
            int r1 = r0 + 8;
            float2 w0 = *reinterpret_cast<const float2*>(W + (size_t)r0 * 4096 + c);
            float2 w1 = *reinterpret_cast<const float2*>(W + (size_t)r1 * 4096 + c);
            __half2 h0 = __floats2half2_rn(w0.x + acc[mt][nt][0],
                                           w0.y + acc[mt][nt][1]);
            __half2 h1 = __floats2half2_rn(w1.x + acc[mt][nt][2],
                                           w1.y + acc[mt][nt][3]);
            *reinterpret_cast<__half2*>(g_Wh + (size_t)r0 * 4096 + c) = h0;
            *reinterpret_cast<__half2*>(g_Wh + (size_t)r1 * 4096 + c) = h1;
        }
    }
}

// ---------------------------------------------------------------------------
// Kernel 3: GEMM  out = Xh * Wh^T + b   (fp16 inputs, fp32 accum)
// TMA-fed 3-stage pipeline (unchanged from R10).
// ---------------------------------------------------------------------------
__global__ void __launch_bounds__(128, 2)
gemm_kernel(const __grid_constant__ CUtensorMap mXh,
            const __grid_constant__ CUtensorMap mWh,
            const float* __restrict__ bias, float* __restrict__ out) {
    extern __shared__ char smem[];
    uint32_t sbase = (uint32_t)__cvta_generic_to_shared(smem);
    int tid = threadIdx.x;
    int lane = tid & 31, warp = tid >> 5;
    int wm = warp >> 1;
    int wn = warp & 1;
    int bm = blockIdx.y, bn = blockIdx.x;

    uint32_t full[NSTAGES] = {sbase, sbase + 8, sbase + 16};

    if (tid == 0) {
        MBAR_INIT(full[0], 1);
        MBAR_INIT(full[1], 1);
        MBAR_INIT(full[2], 1);
    }
    __syncthreads();

    auto issue_stage = [&](int s, int kt) {
        uint32_t st = sbase + SMEM_DATA_OFF + s * SSTAGE;
        MBAR_EXPECT_TX(full[s], SSTAGE);
        tma2d(st,         &mXh, kt * BK, bm * BM, full[s]);
        tma2d(st + 16384, &mWh, kt * BK, bn * BN, full[s]);
    };

    if (tid == 0) {
        issue_stage(0, 0);
        issue_stage(1, 1);
    }

    float acc[4][8][4];
#pragma unroll
    for (int a = 0; a < 4; a++)
#pragma unroll
        for (int b = 0; b < 8; b++)
#pragma unroll
            for (int c = 0; c < 4; c++) acc[a][b][c] = 0.0f;

    int arow = wm * 64 + (lane & 15);
    int nrow0 = wn * 64 + (lane & 7) + ((lane >> 4) << 3);

    uint32_t ah[2][4][4];
    uint32_t bh[2][4][4];
    int ph[NSTAGES] = {0, 0, 0};

    for (int kt = 0; kt < NCHUNK; kt++) {
        int cs = kt % NSTAGES;
        __syncthreads();
        if (tid == 0 && kt + 2 < NCHUNK) issue_stage((kt + 2) % NSTAGES, kt + 2);
        MBAR_WAIT(full[cs], ph[cs]);
        ph[cs] ^= 1;

        uint32_t st = sbase + SMEM_DATA_OFF + cs * SSTAGE;

        auto ldfrag = [&](int buf, int ks) {
            int ach = ks * 2 + (lane >> 4);
            int bch = ks * 2 + ((lane >> 3) & 1);
#pragma unroll
            for (int mt = 0; mt < 4; mt++) {
                int row = arow + mt * 16;
                uint32_t off = row * 128 + ((ach ^ (row & 7)) << 4);
                ldsm4(ah[buf][mt][0], ah[buf][mt][1], ah[buf][mt][2],
                      ah[buf][mt][3], st + off);
            }
#pragma unroll
            for (int q = 0; q < 4; q++) {
                int row = nrow0 + q * 16;
                uint32_t off = row * 128 + ((bch ^ (row & 7)) << 4);
                ldsm4(bh[buf][q][0], bh[buf][q][1], bh[buf][q][2],
                      bh[buf][q][3], st + 16384 + off);
            }
        };

        ldfrag(0, 0);
#pragma unroll
        for (int ks = 0; ks < 4; ks++) {
            int cur = ks & 1, nxt = cur ^ 1;
            if (ks < 3) ldfrag(nxt, ks + 1);
#pragma unroll
            for (int mt = 0; mt < 4; mt++) {
#pragma unroll
                for (int nt = 0; nt < 8; nt++) {
                    int q = nt >> 1, o = (nt & 1) * 2;
                    mma16816(acc[mt][nt], ah[cur][mt], bh[cur][q][o],
                             bh[cur][q][o + 1]);
                }
            }
        }
    }

    const float* bptr = bias + bn * BN + wn * 64;
    size_t outbase = (size_t)(bm * BM + wm * 64) * 4096 + bn * BN + wn * 64;
    int gid = lane >> 2, tig = lane & 3;
#pragma unroll
    for (int nt = 0; nt < 8; nt++) {
        int c = nt * 8 + tig * 2;
        float b0 = bptr[c], b1 = bptr[c + 1];
#pragma unroll
        for (int mt = 0; mt < 4; mt++) {
            int r = mt * 16 + gid;
            float2 v0 = make_float2(acc[mt][nt][0] + b0, acc[mt][nt][1] + b1);
            float2 v1 = make_float2(acc[mt][nt][2] + b0, acc[mt][nt][3] + b1);
            *reinterpret_cast<float2*>(out + outbase + (size_t)r * 4096 + c) = v0;
            *reinterpret_cast<float2*>(out + outbase + (size_t)(r + 8) * 4096 + c) = v1;
        }
    }
}

// ---------------------------------------------------------------------------
typedef CUresult (*EncodeFn)(CUtensorMap*, CUtensorMapDataType, cuuint32_t, void*,
                             const cuuint64_t*, const cuuint64_t*, const cuuint32_t*,
                             const cuuint32_t*, CUtensorMapInterleave, CUtensorMapSwizzle,
                             CUtensorMapL2promotion, CUtensorMapFloatOOBfill);

static void make_map(EncodeFn enc, CUtensorMap* m, void* ptr, uint64_t rows) {
    cuuint64_t dims[2] = {(cuuint64_t)KTOT, (cuuint64_t)rows};
    cuuint64_t strides[1] = {(cuuint64_t)KTOT * 2};
    cuuint32_t box[2] = {BK, BM};
    cuuint32_t es[2] = {1, 1};
    enc(m, CU_TENSOR_MAP_DATA_TYPE_BFLOAT16, 2, ptr, dims, strides, box, es,
        CU_TENSOR_MAP_INTERLEAVE_NONE, CU_TENSOR_MAP_SWIZZLE_128B,
        CU_TENSOR_MAP_L2_PROMOTION_L2_128B, CU_TENSOR_MAP_FLOAT_OOB_FILL_NONE);
}

extern "C" void kernel_launch(void* const* d_in, const int* in_sizes, int n_in,
                              void* d_out, int out_size) {
    const float* x  = (const float*)d_in[0];
    const float* W  = (const float*)d_in[1];
    const float* b  = (const float*)d_in[2];
    const float* Au = (const float*)d_in[3];
    const float* Bu = (const float*)d_in[4];
    const float* A0 = (const float*)d_in[5];
    const float* B0 = (const float*)d_in[6];
    float* out = (float*)d_out;

    void* fp = nullptr;
    cudaDriverEntryPointQueryResult qr;
    cudaGetDriverEntryPoint("cuTensorMapEncodeTiled", &fp, cudaEnableDefault, &qr);
    EncodeFn enc = (EncodeFn)fp;

    void *pXh, *pWh;
    cudaGetSymbolAddress(&pXh, g_Xh);
    cudaGetSymbolAddress(&pWh, g_Wh);
    CUtensorMap mXh, mWh;
    make_map(enc, &mXh, pXh, MTOT);
    make_map(enc, &mWh, pWh, NTOT);

    int n4 = (MTOT * KTOT) / 4;
    split_x_kernel<<<(n4 + 255) / 256, 256>>>((const float4*)x, n4);
    pack_kernel<<<(KTOT * 64 + 255) / 256, 256>>>(Au, Bu, A0, B0);
    build_w_tc_kernel<<<dim3(KTOT / 128, NTOT / 128), 128>>>(W);

    int dsmem = SMEM_DATA_OFF + NSTAGES * SSTAGE;
    cudaFuncSetAttribute(gemm_kernel,
                         cudaFuncAttributeMaxDynamicSharedMemorySize, dsmem);
    gemm_kernel<<<dim3(NTOT / BN, MTOT / BM), 128, dsmem>>>(mXh, mWh, b, out);
}